// round 14
// baseline (speedup 1.0000x reference)
#include <cuda_runtime.h>
#include <cstdint>

// ---------------- constants ----------------
#define B_   8
#define CIN  64
#define COUT 64
#define H_   96
#define W_   96
#define HW   (H_*W_)          // 9216
#define KK   9                // 3x3 taps
#define OFFC 18               // 2*KK offset channels
#define PIT  132              // sS pixel pitch (16B-aligned rows)

// ---------------- f32x2 helpers (Blackwell packed fp32) ----------------
__device__ __forceinline__ unsigned long long fma2(unsigned long long a,
                                                   unsigned long long b,
                                                   unsigned long long c) {
    unsigned long long d;
    asm("fma.rn.f32x2 %0, %1, %2, %3;" : "=l"(d) : "l"(a), "l"(b), "l"(c));
    return d;
}
__device__ __forceinline__ unsigned long long pack2(float lo, float hi) {
    unsigned long long d;
    asm("mov.b64 %0, {%1, %2};" : "=l"(d) : "f"(lo), "f"(hi));
    return d;
}
__device__ __forceinline__ float2 unpack2(unsigned long long v) {
    float2 r;
    asm("mov.b64 {%0, %1}, %2;" : "=f"(r.x), "=f"(r.y) : "l"(v));
    return r;
}

// ---------------- scratch ----------------
__device__ float g_xT[B_ * HW * CIN];       // NHWC transposed x
__device__ float g_off[B_ * OFFC * HW];     // offset field
__device__ float g_wT[KK * CIN * COUT];     // weight as [kk][c][oc]

// ============================================================
// Kernel 1: NCHW -> NHWC transpose of x
// ============================================================
__global__ __launch_bounds__(256) void transpose_x_kernel(const float* __restrict__ x)
{
    __shared__ float tile[32][33];
    int b   = blockIdx.z;
    int hw0 = blockIdx.x * 32;
    int c0  = blockIdx.y * 32;
    int tx = threadIdx.x, ty = threadIdx.y;

    const float* src = x + (size_t)b * CIN * HW;
#pragma unroll
    for (int i = 0; i < 32; i += 8)
        tile[ty + i][tx] = src[(size_t)(c0 + ty + i) * HW + hw0 + tx];
    __syncthreads();
    float* dst = g_xT + (size_t)b * HW * CIN;
#pragma unroll
    for (int i = 0; i < 32; i += 8)
        dst[(size_t)(hw0 + ty + i) * CIN + c0 + tx] = tile[tx][ty + i];
}

// ============================================================
// Kernel 2: weight (oc, c, kk) -> wT[kk][c][oc]
// ============================================================
__global__ __launch_bounds__(256) void transpose_w_kernel(const float* __restrict__ w)
{
    int idx = blockIdx.x * 256 + threadIdx.x;
    if (idx < COUT * CIN * KK) {
        int kk = idx % KK;
        int c  = (idx / KK) % CIN;
        int oc = idx / (KK * CIN);
        g_wT[(kk * CIN + c) * COUT + oc] = w[idx];
    }
}

// ============================================================
// Kernel 3: offset conv with f32x2
// ============================================================
__global__ __launch_bounds__(256) void offset_conv_kernel(
    const float* __restrict__ x,
    const float* __restrict__ off_w,
    const float* __restrict__ off_b)
{
    __shared__ float wS[576][20];

    int tid = threadIdx.x;
    for (int i = tid; i < OFFC * 576; i += 256) {
        int o = i / 576;
        int r = i % 576;
        wS[r][o] = off_w[i];
    }
    for (int r = tid; r < 576; r += 256) { wS[r][18] = 0.f; wS[r][19] = 0.f; }
    __syncthreads();

    int b   = blockIdx.z;
    int wo  = blockIdx.x * 32 + (tid & 31);
    int ho  = blockIdx.y * 8  + (tid >> 5);

    unsigned long long acc2[9];
#pragma unroll
    for (int j = 0; j < 9; ++j) acc2[j] = 0ull;

    const float* xb = x + (size_t)b * CIN * HW;

    for (int c = 0; c < CIN; ++c) {
        const float* xc = xb + (size_t)c * HW;
#pragma unroll
        for (int kh = 0; kh < 3; ++kh) {
            int y = ho + kh - 1;
            bool vy = ((unsigned)y < (unsigned)H_);
#pragma unroll
            for (int kw = 0; kw < 3; ++kw) {
                int xx = wo + kw - 1;
                float xv = 0.f;
                if (vy && (unsigned)xx < (unsigned)W_)
                    xv = __ldg(xc + y * W_ + xx);
                unsigned long long xp = pack2(xv, xv);
                const float* wr = &wS[c * 9 + kh * 3 + kw][0];
                ulonglong2 wA = *(const ulonglong2*)(wr + 0);
                ulonglong2 wB = *(const ulonglong2*)(wr + 4);
                ulonglong2 wC = *(const ulonglong2*)(wr + 8);
                ulonglong2 wD = *(const ulonglong2*)(wr + 12);
                unsigned long long wE = *(const unsigned long long*)(wr + 16);
                acc2[0] = fma2(xp, wA.x, acc2[0]);
                acc2[1] = fma2(xp, wA.y, acc2[1]);
                acc2[2] = fma2(xp, wB.x, acc2[2]);
                acc2[3] = fma2(xp, wB.y, acc2[3]);
                acc2[4] = fma2(xp, wC.x, acc2[4]);
                acc2[5] = fma2(xp, wC.y, acc2[5]);
                acc2[6] = fma2(xp, wD.x, acc2[6]);
                acc2[7] = fma2(xp, wD.y, acc2[7]);
                acc2[8] = fma2(xp, wE,   acc2[8]);
            }
        }
    }

#pragma unroll
    for (int j = 0; j < 9; ++j) {
        float2 f = unpack2(acc2[j]);
        g_off[((size_t)(b * OFFC + 2 * j)     * H_ + ho) * W_ + wo] = f.x + __ldg(&off_b[2 * j]);
        g_off[((size_t)(b * OFFC + 2 * j + 1) * H_ + ho) * W_ + wo] = f.y + __ldg(&off_b[2 * j + 1]);
    }
}

// ============================================================
// Kernel 4: deformable conv main — R12 + 4 CTAs/SM (single-wave grid)
// block: 128 pixels (8 ho x 16 wo) x 64 oc, 256 threads, grid (6,12,8)=576
// smem 54.5KB: sS[64][PIT] + wSh[64][64] + sParO[128][4] + sParW[128][4] + bias
// per tap: threads 0-127 compute per-pixel params (clamped byte offsets +
//          validity-folded weights); threads 128-255 stage the weight chunk.
// gather: branch-free, per pixel 2 broadcast LDS.128 + 4x(2 LDG + 2 FFMA)
// GEMM: thread = 8 pix x 4 oc, f32x2
// ============================================================
__global__ __launch_bounds__(256, 4) void deform_kernel(
    const float* __restrict__ bias,
    float* __restrict__ out)
{
    extern __shared__ float smem[];
    float* sS    = smem;                             // 8448
    float* wSh   = smem + 64 * PIT;                  // 4096
    int*   sParO = (int*)(smem + 64 * PIT + 4096);   // 512 ints
    float* sParW = smem + 64 * PIT + 4096 + 512;     // 512 floats
    float* sBias = smem + 64 * PIT + 4096 + 1024;    // 64 floats

    int tid  = threadIdx.x;
    int warp = tid >> 5;
    int lane = tid & 31;
    int b    = blockIdx.z;
    int wo0  = blockIdx.x * 16;
    int ho0  = blockIdx.y * 8;

    // GEMM mapping: warp = 8 oc-groups (lane&7) x 4 pix-groups (lane>>3)
    int ocg  = (lane & 7) | ((warp & 1) << 3);   // 0..15
    int pixg = (lane >> 3) | ((warp >> 1) << 2); // 0..15
    int oc0  = ocg * 4;
    int p0   = pixg * 8;

    if (tid < 64) sBias[tid] = __ldg(&bias[tid]);

    unsigned long long acc[4][4];   // [pixel-pair q][oc j]
#pragma unroll
    for (int i = 0; i < 4; ++i)
#pragma unroll
        for (int j = 0; j < 4; ++j) acc[i][j] = 0ull;

    const float* offb = g_off + (size_t)b * OFFC * HW;
    const float* xTb  = g_xT + (size_t)b * HW * CIN;
    const char*  xL   = (const char*)(xTb + lane);
    const char*  xH   = (const char*)(xTb + lane + 32);

    for (int kk = 0; kk < KK; ++kk) {
        if (kk > 0) __syncthreads();   // prev GEMM done reading sS/wSh

        if (tid < 128) {
            // ---- per-pixel bilinear setup (1 thread = 1 pixel) ----
            int pix  = tid;
            int ho_s = ho0 + (pix >> 4);
            int wo_s = wo0 + (pix & 15);
            int ky = kk / 3 - 1;
            int kx = kk % 3 - 1;
            float offy = __ldg(offb + (size_t)(2 * kk) * HW + ho_s * W_ + wo_s);
            float offx = __ldg(offb + (size_t)(2 * kk + 1) * HW + ho_s * W_ + wo_s);
            float sy = (float)(ho_s + 1 + ky) + offy;
            float sx = (float)(wo_s + 1 + kx) + offx;
            float y0f = floorf(sy), x0f = floorf(sx);
            float wy1 = sy - y0f, wx1 = sx - x0f;
            float wy0 = 1.f - wy1, wx0 = 1.f - wx1;
            int y0 = (int)y0f, x0 = (int)x0f;
            int y1 = y0 + 1,   x1 = x0 + 1;
            float fy0 = ((unsigned)y0 < (unsigned)H_) ? 1.f : 0.f;
            float fy1 = ((unsigned)y1 < (unsigned)H_) ? 1.f : 0.f;
            float fx0 = ((unsigned)x0 < (unsigned)W_) ? 1.f : 0.f;
            float fx1 = ((unsigned)x1 < (unsigned)W_) ? 1.f : 0.f;
            int y0c = min(max(y0, 0), H_ - 1);
            int y1c = min(max(y1, 0), H_ - 1);
            int x0c = min(max(x0, 0), W_ - 1);
            int x1c = min(max(x1, 0), W_ - 1);
            // byte offsets into NHWC x (CIN*4 = 256 B per pixel)
            int o00 = (y0c * W_ + x0c) * (CIN * 4);
            int o01 = (y0c * W_ + x1c) * (CIN * 4);
            int o10 = (y1c * W_ + x0c) * (CIN * 4);
            int o11 = (y1c * W_ + x1c) * (CIN * 4);
            *(int4*)&sParO[pix * 4] = make_int4(o00, o01, o10, o11);
            *(float4*)&sParW[pix * 4] = make_float4(wy0 * wx0 * fy0 * fx0,
                                                    wy0 * wx1 * fy0 * fx1,
                                                    wy1 * wx0 * fy1 * fx0,
                                                    wy1 * wx1 * fy1 * fx1);
        } else {
            // ---- stage weight chunk wT[kk]: 4096 floats by threads 128-255 ----
            int t2 = tid - 128;
            const float4* src = (const float4*)(g_wT + kk * CIN * COUT);
            float4* dst = (float4*)wSh;
#pragma unroll
            for (int r = 0; r < 8; ++r)
                dst[t2 + r * 128] = src[t2 + r * 128];
        }

        __syncthreads();   // params + weights ready

        // ---- branch-free gather: warp owns 16 pixels as 4 quads ----
#pragma unroll
        for (int t = 0; t < 4; ++t) {
            float aLo[4], aHi[4];
#pragma unroll
            for (int q = 0; q < 4; ++q) {
                int pix = warp * 16 + t * 4 + q;
                int4   offs = *(const int4*)&sParO[pix * 4];
                float4 ws   = *(const float4*)&sParW[pix * 4];
                float aL, aH;
                aL = ws.x * __ldg((const float*)(xL + offs.x));
                aH = ws.x * __ldg((const float*)(xH + offs.x));
                aL = fmaf(ws.y, __ldg((const float*)(xL + offs.y)), aL);
                aH = fmaf(ws.y, __ldg((const float*)(xH + offs.y)), aH);
                aL = fmaf(ws.z, __ldg((const float*)(xL + offs.z)), aL);
                aH = fmaf(ws.z, __ldg((const float*)(xH + offs.z)), aH);
                aL = fmaf(ws.w, __ldg((const float*)(xL + offs.w)), aL);
                aH = fmaf(ws.w, __ldg((const float*)(xH + offs.w)), aH);
                aLo[q] = aL; aHi[q] = aH;
            }
            int col = warp * 16 + t * 4;
            *(float4*)&sS[lane * PIT + col]        = make_float4(aLo[0], aLo[1], aLo[2], aLo[3]);
            *(float4*)&sS[(lane + 32) * PIT + col] = make_float4(aHi[0], aHi[1], aHi[2], aHi[3]);
        }

        __syncthreads();

        // ---- f32x2 GEMM: 8 pix x 4 oc per thread ----
#pragma unroll 4
        for (int c = 0; c < CIN; ++c) {
            ulonglong2 spA = *(const ulonglong2*)&sS[c * PIT + p0];
            ulonglong2 spB = *(const ulonglong2*)&sS[c * PIT + p0 + 4];
            float4 wv = *(const float4*)&wSh[c * 64 + oc0];
            unsigned long long w0 = pack2(wv.x, wv.x);
            unsigned long long w1 = pack2(wv.y, wv.y);
            unsigned long long w2 = pack2(wv.z, wv.z);
            unsigned long long w3 = pack2(wv.w, wv.w);
            acc[0][0] = fma2(spA.x, w0, acc[0][0]);
            acc[0][1] = fma2(spA.x, w1, acc[0][1]);
            acc[0][2] = fma2(spA.x, w2, acc[0][2]);
            acc[0][3] = fma2(spA.x, w3, acc[0][3]);
            acc[1][0] = fma2(spA.y, w0, acc[1][0]);
            acc[1][1] = fma2(spA.y, w1, acc[1][1]);
            acc[1][2] = fma2(spA.y, w2, acc[1][2]);
            acc[1][3] = fma2(spA.y, w3, acc[1][3]);
            acc[2][0] = fma2(spB.x, w0, acc[2][0]);
            acc[2][1] = fma2(spB.x, w1, acc[2][1]);
            acc[2][2] = fma2(spB.x, w2, acc[2][2]);
            acc[2][3] = fma2(spB.x, w3, acc[2][3]);
            acc[3][0] = fma2(spB.y, w0, acc[3][0]);
            acc[3][1] = fma2(spB.y, w1, acc[3][1]);
            acc[3][2] = fma2(spB.y, w2, acc[3][2]);
            acc[3][3] = fma2(spB.y, w3, acc[3][3]);
        }
    }

    // ---- epilogue: write acc to sS as [oc][pix], coalesced NCHW stores ----
    __syncthreads();
#pragma unroll
    for (int q = 0; q < 4; ++q)
#pragma unroll
        for (int j = 0; j < 4; ++j)
            *(unsigned long long*)&sS[(oc0 + j) * PIT + p0 + 2 * q] = acc[q][j];
    __syncthreads();

    float* outb = out + (size_t)b * COUT * HW;
#pragma unroll
    for (int r = 0; r < 32; ++r) {
        int idx = r * 256 + tid;
        int oc  = idx >> 7;
        int pix = idx & 127;
        int ho  = ho0 + (pix >> 4);
        int wo  = wo0 + (pix & 15);
        outb[(size_t)oc * HW + ho * W_ + wo] = sS[oc * PIT + pix] + sBias[oc];
    }
}

// ============================================================
// launch
// ============================================================
extern "C" void kernel_launch(void* const* d_in, const int* in_sizes, int n_in,
                              void* d_out, int out_size)
{
    const float* x      = (const float*)d_in[0];
    const float* weight = (const float*)d_in[1];
    const float* bias   = (const float*)d_in[2];
    const float* off_w  = (const float*)d_in[3];
    const float* off_b  = (const float*)d_in[4];
    float* out = (float*)d_out;

    const int deform_smem = (64 * PIT + 4096 + 512 + 512 + 64) * 4;   // 54528 B
    cudaFuncSetAttribute(deform_kernel,
                         cudaFuncAttributeMaxDynamicSharedMemorySize, deform_smem);

    // 1) layout transforms
    {
        dim3 grid(HW / 32, CIN / 32, B_);
        dim3 block(32, 8);
        transpose_x_kernel<<<grid, block>>>(x);
    }
    {
        int n = COUT * CIN * KK;
        transpose_w_kernel<<<(n + 255) / 256, 256>>>(weight);
    }
    // 2) offset conv
    {
        dim3 grid(W_ / 32, H_ / 8, B_);
        offset_conv_kernel<<<grid, 256>>>(x, off_w, off_b);
    }
    // 3) deformable conv
    {
        dim3 grid(W_ / 16, H_ / 8, B_);
        deform_kernel<<<grid, 256, deform_smem>>>(bias, out);
    }
}

// round 15
// speedup vs baseline: 1.0062x; 1.0062x over previous
#include <cuda_runtime.h>
#include <cstdint>

// ---------------- constants ----------------
#define B_   8
#define CIN  64
#define COUT 64
#define H_   96
#define W_   96
#define HW   (H_*W_)          // 9216
#define KK   9                // 3x3 taps
#define OFFC 18               // 2*KK offset channels
#define PIT  132              // sS pixel pitch (16B-aligned rows)

// ---------------- f32x2 helpers (Blackwell packed fp32) ----------------
__device__ __forceinline__ unsigned long long fma2(unsigned long long a,
                                                   unsigned long long b,
                                                   unsigned long long c) {
    unsigned long long d;
    asm("fma.rn.f32x2 %0, %1, %2, %3;" : "=l"(d) : "l"(a), "l"(b), "l"(c));
    return d;
}
__device__ __forceinline__ unsigned long long pack2(float lo, float hi) {
    unsigned long long d;
    asm("mov.b64 %0, {%1, %2};" : "=l"(d) : "f"(lo), "f"(hi));
    return d;
}
__device__ __forceinline__ float2 unpack2(unsigned long long v) {
    float2 r;
    asm("mov.b64 {%0, %1}, %2;" : "=f"(r.x), "=f"(r.y) : "l"(v));
    return r;
}

// ---------------- scratch ----------------
__device__ float g_xT[B_ * HW * CIN];       // NHWC transposed x
__device__ float g_off[B_ * OFFC * HW];     // offset field
__device__ float g_wT[KK * CIN * COUT];     // weight as [kk][perm(c)][oc]

// ============================================================
// Kernel 1: NCHW -> NHWC transpose of x
// ============================================================
__global__ __launch_bounds__(256) void transpose_x_kernel(const float* __restrict__ x)
{
    __shared__ float tile[32][33];
    int b   = blockIdx.z;
    int hw0 = blockIdx.x * 32;
    int c0  = blockIdx.y * 32;
    int tx = threadIdx.x, ty = threadIdx.y;

    const float* src = x + (size_t)b * CIN * HW;
#pragma unroll
    for (int i = 0; i < 32; i += 8)
        tile[ty + i][tx] = src[(size_t)(c0 + ty + i) * HW + hw0 + tx];
    __syncthreads();
    float* dst = g_xT + (size_t)b * HW * CIN;
#pragma unroll
    for (int i = 0; i < 32; i += 8)
        dst[(size_t)(hw0 + ty + i) * CIN + c0 + tx] = tile[tx][ty + i];
}

// ============================================================
// Kernel 2: weight (oc, c, kk) -> wT[kk][perm(c)][oc]
// perm: channel 2l -> row l, channel 2l+1 -> row l+32 (matches the
// paired-channel gather's register transpose in deform_kernel)
// ============================================================
__global__ __launch_bounds__(256) void transpose_w_kernel(const float* __restrict__ w)
{
    int idx = blockIdx.x * 256 + threadIdx.x;
    if (idx < COUT * CIN * KK) {
        int kk = idx % KK;
        int c  = (idx / KK) % CIN;
        int oc = idx / (KK * CIN);
        int r  = (c & 1) ? (c >> 1) + 32 : (c >> 1);
        g_wT[(kk * CIN + r) * COUT + oc] = w[idx];
    }
}

// ============================================================
// Kernel 3: offset conv with f32x2
// ============================================================
__global__ __launch_bounds__(256) void offset_conv_kernel(
    const float* __restrict__ x,
    const float* __restrict__ off_w,
    const float* __restrict__ off_b)
{
    __shared__ float wS[576][20];

    int tid = threadIdx.x;
    for (int i = tid; i < OFFC * 576; i += 256) {
        int o = i / 576;
        int r = i % 576;
        wS[r][o] = off_w[i];
    }
    for (int r = tid; r < 576; r += 256) { wS[r][18] = 0.f; wS[r][19] = 0.f; }
    __syncthreads();

    int b   = blockIdx.z;
    int wo  = blockIdx.x * 32 + (tid & 31);
    int ho  = blockIdx.y * 8  + (tid >> 5);

    unsigned long long acc2[9];
#pragma unroll
    for (int j = 0; j < 9; ++j) acc2[j] = 0ull;

    const float* xb = x + (size_t)b * CIN * HW;

    for (int c = 0; c < CIN; ++c) {
        const float* xc = xb + (size_t)c * HW;
#pragma unroll
        for (int kh = 0; kh < 3; ++kh) {
            int y = ho + kh - 1;
            bool vy = ((unsigned)y < (unsigned)H_);
#pragma unroll
            for (int kw = 0; kw < 3; ++kw) {
                int xx = wo + kw - 1;
                float xv = 0.f;
                if (vy && (unsigned)xx < (unsigned)W_)
                    xv = __ldg(xc + y * W_ + xx);
                unsigned long long xp = pack2(xv, xv);
                const float* wr = &wS[c * 9 + kh * 3 + kw][0];
                ulonglong2 wA = *(const ulonglong2*)(wr + 0);
                ulonglong2 wB = *(const ulonglong2*)(wr + 4);
                ulonglong2 wC = *(const ulonglong2*)(wr + 8);
                ulonglong2 wD = *(const ulonglong2*)(wr + 12);
                unsigned long long wE = *(const unsigned long long*)(wr + 16);
                acc2[0] = fma2(xp, wA.x, acc2[0]);
                acc2[1] = fma2(xp, wA.y, acc2[1]);
                acc2[2] = fma2(xp, wB.x, acc2[2]);
                acc2[3] = fma2(xp, wB.y, acc2[3]);
                acc2[4] = fma2(xp, wC.x, acc2[4]);
                acc2[5] = fma2(xp, wC.y, acc2[5]);
                acc2[6] = fma2(xp, wD.x, acc2[6]);
                acc2[7] = fma2(xp, wD.y, acc2[7]);
                acc2[8] = fma2(xp, wE,   acc2[8]);
            }
        }
    }

#pragma unroll
    for (int j = 0; j < 9; ++j) {
        float2 f = unpack2(acc2[j]);
        g_off[((size_t)(b * OFFC + 2 * j)     * H_ + ho) * W_ + wo] = f.x + __ldg(&off_b[2 * j]);
        g_off[((size_t)(b * OFFC + 2 * j + 1) * H_ + ho) * W_ + wo] = f.y + __ldg(&off_b[2 * j + 1]);
    }
}

// ============================================================
// Kernel 4: deformable conv main — paired-channel LDG.64 gather
// block: 128 pixels (8 ho x 16 wo) x 64 oc, 256 threads, grid (6,12,8)=576
// smem 54.5KB: sS[64][PIT] + wSh[64][64] + sParO[128][4] + sParW[128][4] + bias
// per tap: threads 0-127 compute per-pixel params; threads 128-255 stage weights.
// gather: lane l loads channel pair (2l,2l+1) via LDG.64, blends 4 corners with
//         fma2 (half the instructions of R12), register-transposes into rows
//         l / l+32 (conflict-free STS.128; weights pre-permuted to match).
// GEMM: thread = 8 pix x 4 oc, f32x2
// ============================================================
__global__ __launch_bounds__(256, 3) void deform_kernel(
    const float* __restrict__ bias,
    float* __restrict__ out)
{
    extern __shared__ float smem[];
    float* sS    = smem;                             // 8448
    float* wSh   = smem + 64 * PIT;                  // 4096
    int*   sParO = (int*)(smem + 64 * PIT + 4096);   // 512 ints
    float* sParW = smem + 64 * PIT + 4096 + 512;     // 512 floats
    float* sBias = smem + 64 * PIT + 4096 + 1024;    // 64 floats

    int tid  = threadIdx.x;
    int warp = tid >> 5;
    int lane = tid & 31;
    int b    = blockIdx.z;
    int wo0  = blockIdx.x * 16;
    int ho0  = blockIdx.y * 8;

    // GEMM mapping: warp = 8 oc-groups (lane&7) x 4 pix-groups (lane>>3)
    int ocg  = (lane & 7) | ((warp & 1) << 3);   // 0..15
    int pixg = (lane >> 3) | ((warp >> 1) << 2); // 0..15
    int oc0  = ocg * 4;
    int p0   = pixg * 8;

    if (tid < 64) sBias[tid] = __ldg(&bias[tid]);

    unsigned long long acc[4][4];   // [pixel-pair q][oc j]
#pragma unroll
    for (int i = 0; i < 4; ++i)
#pragma unroll
        for (int j = 0; j < 4; ++j) acc[i][j] = 0ull;

    const float* offb = g_off + (size_t)b * OFFC * HW;
    const float* xTb  = g_xT + (size_t)b * HW * CIN;
    const char*  xP   = (const char*)xTb + lane * 8;   // channel pair (2l, 2l+1)

    for (int kk = 0; kk < KK; ++kk) {
        if (kk > 0) __syncthreads();   // prev GEMM done reading sS/wSh

        if (tid < 128) {
            // ---- per-pixel bilinear setup (1 thread = 1 pixel) ----
            int pix  = tid;
            int ho_s = ho0 + (pix >> 4);
            int wo_s = wo0 + (pix & 15);
            int ky = kk / 3 - 1;
            int kx = kk % 3 - 1;
            float offy = __ldg(offb + (size_t)(2 * kk) * HW + ho_s * W_ + wo_s);
            float offx = __ldg(offb + (size_t)(2 * kk + 1) * HW + ho_s * W_ + wo_s);
            float sy = (float)(ho_s + 1 + ky) + offy;
            float sx = (float)(wo_s + 1 + kx) + offx;
            float y0f = floorf(sy), x0f = floorf(sx);
            float wy1 = sy - y0f, wx1 = sx - x0f;
            float wy0 = 1.f - wy1, wx0 = 1.f - wx1;
            int y0 = (int)y0f, x0 = (int)x0f;
            int y1 = y0 + 1,   x1 = x0 + 1;
            float fy0 = ((unsigned)y0 < (unsigned)H_) ? 1.f : 0.f;
            float fy1 = ((unsigned)y1 < (unsigned)H_) ? 1.f : 0.f;
            float fx0 = ((unsigned)x0 < (unsigned)W_) ? 1.f : 0.f;
            float fx1 = ((unsigned)x1 < (unsigned)W_) ? 1.f : 0.f;
            int y0c = min(max(y0, 0), H_ - 1);
            int y1c = min(max(y1, 0), H_ - 1);
            int x0c = min(max(x0, 0), W_ - 1);
            int x1c = min(max(x1, 0), W_ - 1);
            // byte offsets into NHWC x (CIN*4 = 256 B per pixel)
            int o00 = (y0c * W_ + x0c) * (CIN * 4);
            int o01 = (y0c * W_ + x1c) * (CIN * 4);
            int o10 = (y1c * W_ + x0c) * (CIN * 4);
            int o11 = (y1c * W_ + x1c) * (CIN * 4);
            *(int4*)&sParO[pix * 4] = make_int4(o00, o01, o10, o11);
            *(float4*)&sParW[pix * 4] = make_float4(wy0 * wx0 * fy0 * fx0,
                                                    wy0 * wx1 * fy0 * fx1,
                                                    wy1 * wx0 * fy1 * fx0,
                                                    wy1 * wx1 * fy1 * fx1);
        } else {
            // ---- stage weight chunk wT[kk]: 4096 floats by threads 128-255 ----
            int t2 = tid - 128;
            const float4* src = (const float4*)(g_wT + kk * CIN * COUT);
            float4* dst = (float4*)wSh;
#pragma unroll
            for (int r = 0; r < 8; ++r)
                dst[t2 + r * 128] = src[t2 + r * 128];
        }

        __syncthreads();   // params + weights ready

        // ---- paired-channel gather: warp owns 16 pixels as 4 quads ----
#pragma unroll
        for (int t = 0; t < 4; ++t) {
            unsigned long long v[4];
#pragma unroll
            for (int q = 0; q < 4; ++q) {
                int pix = warp * 16 + t * 4 + q;
                int4   offs = *(const int4*)&sParO[pix * 4];
                float4 ws   = *(const float4*)&sParW[pix * 4];
                unsigned long long a;
                a = fma2(__ldg((const unsigned long long*)(xP + offs.x)), pack2(ws.x, ws.x), 0ull);
                a = fma2(__ldg((const unsigned long long*)(xP + offs.y)), pack2(ws.y, ws.y), a);
                a = fma2(__ldg((const unsigned long long*)(xP + offs.z)), pack2(ws.z, ws.z), a);
                a = fma2(__ldg((const unsigned long long*)(xP + offs.w)), pack2(ws.w, ws.w), a);
                v[q] = a;
            }
            float2 f0 = unpack2(v[0]);
            float2 f1 = unpack2(v[1]);
            float2 f2 = unpack2(v[2]);
            float2 f3 = unpack2(v[3]);
            int col = warp * 16 + t * 4;
            // channel 2l -> row l, channel 2l+1 -> row l+32 (weights pre-permuted)
            *(float4*)&sS[lane * PIT + col]        = make_float4(f0.x, f1.x, f2.x, f3.x);
            *(float4*)&sS[(lane + 32) * PIT + col] = make_float4(f0.y, f1.y, f2.y, f3.y);
        }

        __syncthreads();

        // ---- f32x2 GEMM: 8 pix x 4 oc per thread ----
#pragma unroll 4
        for (int c = 0; c < CIN; ++c) {
            ulonglong2 spA = *(const ulonglong2*)&sS[c * PIT + p0];
            ulonglong2 spB = *(const ulonglong2*)&sS[c * PIT + p0 + 4];
            float4 wv = *(const float4*)&wSh[c * 64 + oc0];
            unsigned long long w0 = pack2(wv.x, wv.x);
            unsigned long long w1 = pack2(wv.y, wv.y);
            unsigned long long w2 = pack2(wv.z, wv.z);
            unsigned long long w3 = pack2(wv.w, wv.w);
            acc[0][0] = fma2(spA.x, w0, acc[0][0]);
            acc[0][1] = fma2(spA.x, w1, acc[0][1]);
            acc[0][2] = fma2(spA.x, w2, acc[0][2]);
            acc[0][3] = fma2(spA.x, w3, acc[0][3]);
            acc[1][0] = fma2(spA.y, w0, acc[1][0]);
            acc[1][1] = fma2(spA.y, w1, acc[1][1]);
            acc[1][2] = fma2(spA.y, w2, acc[1][2]);
            acc[1][3] = fma2(spA.y, w3, acc[1][3]);
            acc[2][0] = fma2(spB.x, w0, acc[2][0]);
            acc[2][1] = fma2(spB.x, w1, acc[2][1]);
            acc[2][2] = fma2(spB.x, w2, acc[2][2]);
            acc[2][3] = fma2(spB.x, w3, acc[2][3]);
            acc[3][0] = fma2(spB.y, w0, acc[3][0]);
            acc[3][1] = fma2(spB.y, w1, acc[3][1]);
            acc[3][2] = fma2(spB.y, w2, acc[3][2]);
            acc[3][3] = fma2(spB.y, w3, acc[3][3]);
        }
    }

    // ---- epilogue: write acc to sS as [oc][pix], coalesced NCHW stores ----
    __syncthreads();
#pragma unroll
    for (int q = 0; q < 4; ++q)
#pragma unroll
        for (int j = 0; j < 4; ++j)
            *(unsigned long long*)&sS[(oc0 + j) * PIT + p0 + 2 * q] = acc[q][j];
    __syncthreads();

    float* outb = out + (size_t)b * COUT * HW;
#pragma unroll
    for (int r = 0; r < 32; ++r) {
        int idx = r * 256 + tid;
        int oc  = idx >> 7;
        int pix = idx & 127;
        int ho  = ho0 + (pix >> 4);
        int wo  = wo0 + (pix & 15);
        outb[(size_t)oc * HW + ho * W_ + wo] = sS[oc * PIT + pix] + sBias[oc];
    }
}

// ============================================================
// launch
// ============================================================
extern "C" void kernel_launch(void* const* d_in, const int* in_sizes, int n_in,
                              void* d_out, int out_size)
{
    const float* x      = (const float*)d_in[0];
    const float* weight = (const float*)d_in[1];
    const float* bias   = (const float*)d_in[2];
    const float* off_w  = (const float*)d_in[3];
    const float* off_b  = (const float*)d_in[4];
    float* out = (float*)d_out;

    const int deform_smem = (64 * PIT + 4096 + 512 + 512 + 64) * 4;   // 54528 B
    cudaFuncSetAttribute(deform_kernel,
                         cudaFuncAttributeMaxDynamicSharedMemorySize, deform_smem);

    // 1) layout transforms
    {
        dim3 grid(HW / 32, CIN / 32, B_);
        dim3 block(32, 8);
        transpose_x_kernel<<<grid, block>>>(x);
    }
    {
        int n = COUT * CIN * KK;
        transpose_w_kernel<<<(n + 255) / 256, 256>>>(weight);
    }
    // 2) offset conv
    {
        dim3 grid(W_ / 32, H_ / 8, B_);
        offset_conv_kernel<<<grid, 256>>>(x, off_w, off_b);
    }
    // 3) deformable conv
    {
        dim3 grid(W_ / 16, H_ / 8, B_);
        deform_kernel<<<grid, 256, deform_smem>>>(bias, out);
    }
}

// round 16
// speedup vs baseline: 1.0283x; 1.0220x over previous
#include <cuda_runtime.h>
#include <cstdint>

// ---------------- constants ----------------
#define B_   8
#define CIN  64
#define COUT 64
#define H_   96
#define W_   96
#define HW   (H_*W_)          // 9216
#define KK   9                // 3x3 taps
#define OFFC 18               // 2*KK offset channels
#define PIT  132              // sS pixel pitch (16B-aligned rows)

// ---------------- f32x2 helpers (Blackwell packed fp32) ----------------
__device__ __forceinline__ unsigned long long fma2(unsigned long long a,
                                                   unsigned long long b,
                                                   unsigned long long c) {
    unsigned long long d;
    asm("fma.rn.f32x2 %0, %1, %2, %3;" : "=l"(d) : "l"(a), "l"(b), "l"(c));
    return d;
}
__device__ __forceinline__ unsigned long long pack2(float lo, float hi) {
    unsigned long long d;
    asm("mov.b64 %0, {%1, %2};" : "=l"(d) : "f"(lo), "f"(hi));
    return d;
}
__device__ __forceinline__ float2 unpack2(unsigned long long v) {
    float2 r;
    asm("mov.b64 {%0, %1}, %2;" : "=f"(r.x), "=f"(r.y) : "l"(v));
    return r;
}

// ---------------- scratch ----------------
__device__ float g_xT[B_ * HW * CIN];       // NHWC transposed x
__device__ float g_off[B_ * OFFC * HW];     // offset field
__device__ float g_wT[KK * CIN * COUT];     // weight as [kk][c][oc]

// ============================================================
// Kernel 1: NCHW -> NHWC transpose of x
// ============================================================
__global__ __launch_bounds__(256) void transpose_x_kernel(const float* __restrict__ x)
{
    __shared__ float tile[32][33];
    int b   = blockIdx.z;
    int hw0 = blockIdx.x * 32;
    int c0  = blockIdx.y * 32;
    int tx = threadIdx.x, ty = threadIdx.y;

    const float* src = x + (size_t)b * CIN * HW;
#pragma unroll
    for (int i = 0; i < 32; i += 8)
        tile[ty + i][tx] = src[(size_t)(c0 + ty + i) * HW + hw0 + tx];
    __syncthreads();
    float* dst = g_xT + (size_t)b * HW * CIN;
#pragma unroll
    for (int i = 0; i < 32; i += 8)
        dst[(size_t)(hw0 + ty + i) * CIN + c0 + tx] = tile[tx][ty + i];
}

// ============================================================
// Kernel 2: weight (oc, c, kk) -> wT[kk][c][oc]
// ============================================================
__global__ __launch_bounds__(256) void transpose_w_kernel(const float* __restrict__ w)
{
    int idx = blockIdx.x * 256 + threadIdx.x;
    if (idx < COUT * CIN * KK) {
        int kk = idx % KK;
        int c  = (idx / KK) % CIN;
        int oc = idx / (KK * CIN);
        g_wT[(kk * CIN + c) * COUT + oc] = w[idx];
    }
}

// ============================================================
// Kernel 3: offset conv, f32x2, 2 pixels per thread
// block: 256 threads = 32 wo x 8 ty; thread handles rows (ho0+ty, ho0+ty+8)
// grid (3, 6, 8) = 144 blocks -> ~1 block/SM, single wave
// weight LDS (5 per (c,tap)) shared across both pixels
// ============================================================
__global__ __launch_bounds__(256) void offset_conv_kernel(
    const float* __restrict__ x,
    const float* __restrict__ off_w,
    const float* __restrict__ off_b)
{
    __shared__ float wS[576][20];   // 46080 B

    int tid = threadIdx.x;
    for (int i = tid; i < OFFC * 576; i += 256) {
        int o = i / 576;
        int r = i % 576;
        wS[r][o] = off_w[i];
    }
    for (int r = tid; r < 576; r += 256) { wS[r][18] = 0.f; wS[r][19] = 0.f; }
    __syncthreads();

    int b    = blockIdx.z;
    int wo   = blockIdx.x * 32 + (tid & 31);
    int hoA  = blockIdx.y * 16 + (tid >> 5);      // rows hoA and hoA+8
    int hoB  = hoA + 8;

    unsigned long long accA[9], accB[9];
#pragma unroll
    for (int j = 0; j < 9; ++j) { accA[j] = 0ull; accB[j] = 0ull; }

    const float* xb = x + (size_t)b * CIN * HW;

    for (int c = 0; c < CIN; ++c) {
        const float* xc = xb + (size_t)c * HW;
#pragma unroll
        for (int kh = 0; kh < 3; ++kh) {
            int yA = hoA + kh - 1;
            int yB = hoB + kh - 1;
            bool vyA = ((unsigned)yA < (unsigned)H_);
            bool vyB = ((unsigned)yB < (unsigned)H_);
#pragma unroll
            for (int kw = 0; kw < 3; ++kw) {
                int xx = wo + kw - 1;
                bool vx = ((unsigned)xx < (unsigned)W_);
                float xvA = (vyA && vx) ? __ldg(xc + yA * W_ + xx) : 0.f;
                float xvB = (vyB && vx) ? __ldg(xc + yB * W_ + xx) : 0.f;
                unsigned long long xpA = pack2(xvA, xvA);
                unsigned long long xpB = pack2(xvB, xvB);
                const float* wr = &wS[c * 9 + kh * 3 + kw][0];
                ulonglong2 wA = *(const ulonglong2*)(wr + 0);
                ulonglong2 wB = *(const ulonglong2*)(wr + 4);
                ulonglong2 wC = *(const ulonglong2*)(wr + 8);
                ulonglong2 wD = *(const ulonglong2*)(wr + 12);
                unsigned long long wE = *(const unsigned long long*)(wr + 16);
                accA[0] = fma2(xpA, wA.x, accA[0]);  accB[0] = fma2(xpB, wA.x, accB[0]);
                accA[1] = fma2(xpA, wA.y, accA[1]);  accB[1] = fma2(xpB, wA.y, accB[1]);
                accA[2] = fma2(xpA, wB.x, accA[2]);  accB[2] = fma2(xpB, wB.x, accB[2]);
                accA[3] = fma2(xpA, wB.y, accA[3]);  accB[3] = fma2(xpB, wB.y, accB[3]);
                accA[4] = fma2(xpA, wC.x, accA[4]);  accB[4] = fma2(xpB, wC.x, accB[4]);
                accA[5] = fma2(xpA, wC.y, accA[5]);  accB[5] = fma2(xpB, wC.y, accB[5]);
                accA[6] = fma2(xpA, wD.x, accA[6]);  accB[6] = fma2(xpB, wD.x, accB[6]);
                accA[7] = fma2(xpA, wD.y, accA[7]);  accB[7] = fma2(xpB, wD.y, accB[7]);
                accA[8] = fma2(xpA, wE,   accA[8]);  accB[8] = fma2(xpB, wE,   accB[8]);
            }
        }
    }

#pragma unroll
    for (int j = 0; j < 9; ++j) {
        float2 fA = unpack2(accA[j]);
        float2 fB = unpack2(accB[j]);
        float b0 = __ldg(&off_b[2 * j]);
        float b1 = __ldg(&off_b[2 * j + 1]);
        g_off[((size_t)(b * OFFC + 2 * j)     * H_ + hoA) * W_ + wo] = fA.x + b0;
        g_off[((size_t)(b * OFFC + 2 * j + 1) * H_ + hoA) * W_ + wo] = fA.y + b1;
        g_off[((size_t)(b * OFFC + 2 * j)     * H_ + hoB) * W_ + wo] = fB.x + b0;
        g_off[((size_t)(b * OFFC + 2 * j + 1) * H_ + hoB) * W_ + wo] = fB.y + b1;
    }
}

// ============================================================
// Kernel 4: deformable conv main — R12 (best) + smem bias + GEMM unroll 8
// block: 128 pixels (8 ho x 16 wo) x 64 oc, 256 threads, grid (6,12,8)=576
// smem 54.5KB: sS[64][PIT] + wSh[64][64] + sParO[128][4] + sParW[128][4] + bias
// per tap: threads 0-127 compute per-pixel params; threads 128-255 stage weights.
// gather: branch-free, per pixel 2 broadcast LDS.128 + 4x(2 LDG.32 + 2 FFMA)
// GEMM: thread = 8 pix x 4 oc, f32x2
// ============================================================
__global__ __launch_bounds__(256, 3) void deform_kernel(
    const float* __restrict__ bias,
    float* __restrict__ out)
{
    extern __shared__ float smem[];
    float* sS    = smem;                             // 8448
    float* wSh   = smem + 64 * PIT;                  // 4096
    int*   sParO = (int*)(smem + 64 * PIT + 4096);   // 512 ints
    float* sParW = smem + 64 * PIT + 4096 + 512;     // 512 floats
    float* sBias = smem + 64 * PIT + 4096 + 1024;    // 64 floats

    int tid  = threadIdx.x;
    int warp = tid >> 5;
    int lane = tid & 31;
    int b    = blockIdx.z;
    int wo0  = blockIdx.x * 16;
    int ho0  = blockIdx.y * 8;

    // GEMM mapping: warp = 8 oc-groups (lane&7) x 4 pix-groups (lane>>3)
    int ocg  = (lane & 7) | ((warp & 1) << 3);   // 0..15
    int pixg = (lane >> 3) | ((warp >> 1) << 2); // 0..15
    int oc0  = ocg * 4;
    int p0   = pixg * 8;

    if (tid < 64) sBias[tid] = __ldg(&bias[tid]);

    unsigned long long acc[4][4];   // [pixel-pair q][oc j]
#pragma unroll
    for (int i = 0; i < 4; ++i)
#pragma unroll
        for (int j = 0; j < 4; ++j) acc[i][j] = 0ull;

    const float* offb = g_off + (size_t)b * OFFC * HW;
    const float* xTb  = g_xT + (size_t)b * HW * CIN;
    const char*  xL   = (const char*)(xTb + lane);
    const char*  xH   = (const char*)(xTb + lane + 32);

    for (int kk = 0; kk < KK; ++kk) {
        if (kk > 0) __syncthreads();   // prev GEMM done reading sS/wSh

        if (tid < 128) {
            // ---- per-pixel bilinear setup (1 thread = 1 pixel) ----
            int pix  = tid;
            int ho_s = ho0 + (pix >> 4);
            int wo_s = wo0 + (pix & 15);
            int ky = kk / 3 - 1;
            int kx = kk % 3 - 1;
            float offy = __ldg(offb + (size_t)(2 * kk) * HW + ho_s * W_ + wo_s);
            float offx = __ldg(offb + (size_t)(2 * kk + 1) * HW + ho_s * W_ + wo_s);
            float sy = (float)(ho_s + 1 + ky) + offy;
            float sx = (float)(wo_s + 1 + kx) + offx;
            float y0f = floorf(sy), x0f = floorf(sx);
            float wy1 = sy - y0f, wx1 = sx - x0f;
            float wy0 = 1.f - wy1, wx0 = 1.f - wx1;
            int y0 = (int)y0f, x0 = (int)x0f;
            int y1 = y0 + 1,   x1 = x0 + 1;
            float fy0 = ((unsigned)y0 < (unsigned)H_) ? 1.f : 0.f;
            float fy1 = ((unsigned)y1 < (unsigned)H_) ? 1.f : 0.f;
            float fx0 = ((unsigned)x0 < (unsigned)W_) ? 1.f : 0.f;
            float fx1 = ((unsigned)x1 < (unsigned)W_) ? 1.f : 0.f;
            int y0c = min(max(y0, 0), H_ - 1);
            int y1c = min(max(y1, 0), H_ - 1);
            int x0c = min(max(x0, 0), W_ - 1);
            int x1c = min(max(x1, 0), W_ - 1);
            // byte offsets into NHWC x (CIN*4 = 256 B per pixel)
            int o00 = (y0c * W_ + x0c) * (CIN * 4);
            int o01 = (y0c * W_ + x1c) * (CIN * 4);
            int o10 = (y1c * W_ + x0c) * (CIN * 4);
            int o11 = (y1c * W_ + x1c) * (CIN * 4);
            *(int4*)&sParO[pix * 4] = make_int4(o00, o01, o10, o11);
            *(float4*)&sParW[pix * 4] = make_float4(wy0 * wx0 * fy0 * fx0,
                                                    wy0 * wx1 * fy0 * fx1,
                                                    wy1 * wx0 * fy1 * fx0,
                                                    wy1 * wx1 * fy1 * fx1);
        } else {
            // ---- stage weight chunk wT[kk]: 4096 floats by threads 128-255 ----
            int t2 = tid - 128;
            const float4* src = (const float4*)(g_wT + kk * CIN * COUT);
            float4* dst = (float4*)wSh;
#pragma unroll
            for (int r = 0; r < 8; ++r)
                dst[t2 + r * 128] = src[t2 + r * 128];
        }

        __syncthreads();   // params + weights ready

        // ---- branch-free gather: warp owns 16 pixels as 4 quads ----
#pragma unroll
        for (int t = 0; t < 4; ++t) {
            float aLo[4], aHi[4];
#pragma unroll
            for (int q = 0; q < 4; ++q) {
                int pix = warp * 16 + t * 4 + q;
                int4   offs = *(const int4*)&sParO[pix * 4];
                float4 ws   = *(const float4*)&sParW[pix * 4];
                float aL, aH;
                aL = ws.x * __ldg((const float*)(xL + offs.x));
                aH = ws.x * __ldg((const float*)(xH + offs.x));
                aL = fmaf(ws.y, __ldg((const float*)(xL + offs.y)), aL);
                aH = fmaf(ws.y, __ldg((const float*)(xH + offs.y)), aH);
                aL = fmaf(ws.z, __ldg((const float*)(xL + offs.z)), aL);
                aH = fmaf(ws.z, __ldg((const float*)(xH + offs.z)), aH);
                aL = fmaf(ws.w, __ldg((const float*)(xL + offs.w)), aL);
                aH = fmaf(ws.w, __ldg((const float*)(xH + offs.w)), aH);
                aLo[q] = aL; aHi[q] = aH;
            }
            int col = warp * 16 + t * 4;
            *(float4*)&sS[lane * PIT + col]        = make_float4(aLo[0], aLo[1], aLo[2], aLo[3]);
            *(float4*)&sS[(lane + 32) * PIT + col] = make_float4(aHi[0], aHi[1], aHi[2], aHi[3]);
        }

        __syncthreads();

        // ---- f32x2 GEMM: 8 pix x 4 oc per thread ----
#pragma unroll 8
        for (int c = 0; c < CIN; ++c) {
            ulonglong2 spA = *(const ulonglong2*)&sS[c * PIT + p0];
            ulonglong2 spB = *(const ulonglong2*)&sS[c * PIT + p0 + 4];
            float4 wv = *(const float4*)&wSh[c * 64 + oc0];
            unsigned long long w0 = pack2(wv.x, wv.x);
            unsigned long long w1 = pack2(wv.y, wv.y);
            unsigned long long w2 = pack2(wv.z, wv.z);
            unsigned long long w3 = pack2(wv.w, wv.w);
            acc[0][0] = fma2(spA.x, w0, acc[0][0]);
            acc[0][1] = fma2(spA.x, w1, acc[0][1]);
            acc[0][2] = fma2(spA.x, w2, acc[0][2]);
            acc[0][3] = fma2(spA.x, w3, acc[0][3]);
            acc[1][0] = fma2(spA.y, w0, acc[1][0]);
            acc[1][1] = fma2(spA.y, w1, acc[1][1]);
            acc[1][2] = fma2(spA.y, w2, acc[1][2]);
            acc[1][3] = fma2(spA.y, w3, acc[1][3]);
            acc[2][0] = fma2(spB.x, w0, acc[2][0]);
            acc[2][1] = fma2(spB.x, w1, acc[2][1]);
            acc[2][2] = fma2(spB.x, w2, acc[2][2]);
            acc[2][3] = fma2(spB.x, w3, acc[2][3]);
            acc[3][0] = fma2(spB.y, w0, acc[3][0]);
            acc[3][1] = fma2(spB.y, w1, acc[3][1]);
            acc[3][2] = fma2(spB.y, w2, acc[3][2]);
            acc[3][3] = fma2(spB.y, w3, acc[3][3]);
        }
    }

    // ---- epilogue: write acc to sS as [oc][pix], coalesced NCHW stores ----
    __syncthreads();
#pragma unroll
    for (int q = 0; q < 4; ++q)
#pragma unroll
        for (int j = 0; j < 4; ++j)
            *(unsigned long long*)&sS[(oc0 + j) * PIT + p0 + 2 * q] = acc[q][j];
    __syncthreads();

    float* outb = out + (size_t)b * COUT * HW;
#pragma unroll
    for (int r = 0; r < 32; ++r) {
        int idx = r * 256 + tid;
        int oc  = idx >> 7;
        int pix = idx & 127;
        int ho  = ho0 + (pix >> 4);
        int wo  = wo0 + (pix & 15);
        outb[(size_t)oc * HW + ho * W_ + wo] = sS[oc * PIT + pix] + sBias[oc];
    }
}

// ============================================================
// launch
// ============================================================
extern "C" void kernel_launch(void* const* d_in, const int* in_sizes, int n_in,
                              void* d_out, int out_size)
{
    const float* x      = (const float*)d_in[0];
    const float* weight = (const float*)d_in[1];
    const float* bias   = (const float*)d_in[2];
    const float* off_w  = (const float*)d_in[3];
    const float* off_b  = (const float*)d_in[4];
    float* out = (float*)d_out;

    const int deform_smem = (64 * PIT + 4096 + 512 + 512 + 64) * 4;   // 54528 B
    cudaFuncSetAttribute(deform_kernel,
                         cudaFuncAttributeMaxDynamicSharedMemorySize, deform_smem);

    // 1) layout transforms
    {
        dim3 grid(HW / 32, CIN / 32, B_);
        dim3 block(32, 8);
        transpose_x_kernel<<<grid, block>>>(x);
    }
    {
        int n = COUT * CIN * KK;
        transpose_w_kernel<<<(n + 255) / 256, 256>>>(weight);
    }
    // 2) offset conv (2 pixels/thread, 144 blocks)
    {
        dim3 grid(W_ / 32, H_ / 16, B_);
        offset_conv_kernel<<<grid, 256>>>(x, off_w, off_b);
    }
    // 3) deformable conv
    {
        dim3 grid(W_ / 16, H_ / 8, B_);
        deform_kernel<<<grid, 256, deform_smem>>>(bias, out);
    }
}